// round 16
// baseline (speedup 1.0000x reference)
#include <cuda_runtime.h>
#include <cuda_fp16.h>
#include <cuda_bf16.h>
#include <cuda_fp8.h>
#include <cstdint>

#define M_DIM 4096
#define H_DIM 4096
#define I_DIM 14336
#define KB_H (H_DIM/128)
#define KB_I (I_DIM/128)

// ---- static scratch: quantized tensors as r-major-permuted e4m3 bytes ----
// within each 128-byte K-chunk row, col c (ks=c>>4, cc=c&15, r=(cc&7)>>1,
// hi=cc>>3, lo=cc&1) lives at byte  r*32 + ks*4 + hi*2 + lo.
__device__ int g_fmt;
__device__ uint8_t g_wg[(size_t)I_DIM*H_DIM];
__device__ uint8_t g_wu[(size_t)I_DIM*H_DIM];
__device__ uint8_t g_wd[(size_t)H_DIM*I_DIM];
__device__ uint8_t g_xq[(size_t)M_DIM*H_DIM];
__device__ float   g_xs[(size_t)M_DIM*KB_H];
__device__ uint8_t g_hq[(size_t)M_DIM*I_DIM];
__device__ float   g_hs[(size_t)M_DIM*KB_I];

// ---- scalar helpers ----
__device__ __forceinline__ float fp8_to_f32(unsigned char b){
    __half_raw hr = __nv_cvt_fp8_to_halfraw((__nv_fp8_storage_t)b, __NV_E4M3);
    return __half2float(*(__half*)&hr);
}
__device__ __forceinline__ bool fp8_rt(float v){
    if(!isfinite(v) || fabsf(v) > 448.0f) return false;
    __nv_fp8_storage_t b = __nv_cvt_float_to_fp8(v, __NV_SATFINITE, __NV_E4M3);
    return fp8_to_f32((unsigned char)b) == v;
}
__device__ __forceinline__ uint32_t fq8(float v, float s){
    return (uint32_t)(uint8_t)__nv_cvt_float_to_fp8(__fdiv_rn(v, s), __NV_SATFINITE, __NV_E4M3);
}
__device__ __forceinline__ uint32_t f2e4m3(float v){
    return (uint32_t)(uint8_t)__nv_cvt_float_to_fp8(v, __NV_SATFINITE, __NV_E4M3);
}
__device__ __forceinline__ float exp_precise(float x){
    float n = rintf(x * 1.4426950408889634f);
    float r = fmaf(n, -0.693359375f, x);
    r = fmaf(n, 2.12194440e-4f, r);
    float p = 1.9841269841e-4f;
    p = fmaf(p, r, 1.3888888888e-3f);
    p = fmaf(p, r, 8.3333333333e-3f);
    p = fmaf(p, r, 4.1666666667e-2f);
    p = fmaf(p, r, 1.6666666667e-1f);
    p = fmaf(p, r, 0.5f);
    p = fmaf(p, r, 1.0f);
    p = fmaf(p, r, 1.0f);
    return ldexpf(p, (int)n);
}
__device__ __forceinline__ float sigmoid_precise(float x){
    float ax = fminf(fabsf(x), 87.0f);
    float e = exp_precise(-ax);
    float den = 1.0f + e;
    return (x >= 0.0f) ? __fdiv_rn(1.0f, den) : __fdiv_rn(e, den);
}
__device__ __forceinline__ void cpasync16(void* s, const void* g){
    unsigned sa = (unsigned)__cvta_generic_to_shared(s);
    asm volatile("cp.async.cg.shared.global [%0], [%1], 16;\n" :: "r"(sa), "l"(g));
}
__device__ __forceinline__ unsigned cvt8(unsigned short s){
    unsigned r;
    asm("cvt.rn.f16x2.e4m3x2 %0, %1;" : "=r"(r) : "h"(s));
    return r;
}
__device__ __forceinline__ void mma_f16(float* c, unsigned a0, unsigned a1, unsigned a2, unsigned a3,
                                        unsigned b0, unsigned b1){
    asm volatile("mma.sync.aligned.m16n8k16.row.col.f32.f16.f16.f32 "
        "{%0,%1,%2,%3}, {%4,%5,%6,%7}, {%8,%9}, {%0,%1,%2,%3};\n"
        : "+f"(c[0]), "+f"(c[1]), "+f"(c[2]), "+f"(c[3])
        : "r"(a0), "r"(a1), "r"(a2), "r"(a3), "r"(b0), "r"(b1));
}

// ---- format detection ----
__global__ void k_detect(const void* __restrict__ w){
    int tid = threadIdx.x;
    int ok32 = 1, ok16 = 1;
    for(int i = tid; i < 2048; i += blockDim.x){
        ok32 = ok32 && fp8_rt(((const float*)w)[i]);
        ok16 = ok16 && fp8_rt(__bfloat162float(((const __nv_bfloat16*)w)[i]));
    }
    int a32 = __syncthreads_and(ok32);
    int a16 = __syncthreads_and(ok16);
    if(tid == 0) g_fmt = a32 ? 1 : (a16 ? 2 : 0);
}

// ---- weight convert -> r-major permuted e4m3 bytes (exact) ----
__global__ void k_convert(const void* __restrict__ src, uint8_t* __restrict__ dst, size_t n){
    int fmt = g_fmt;
    size_t i = (size_t)blockIdx.x*blockDim.x + threadIdx.x;
    size_t stride = (size_t)gridDim.x*blockDim.x;
    size_t nw = n >> 2;
    for(size_t widx = i; widx < nw; widx += stride){
        size_t chunk = widx >> 5;
        int o = (int)(widx & 31);
        int r = o >> 3, ks = o & 7;
        size_t cb = chunk*128 + (size_t)ks*16 + 2*r;
        uint32_t w;
        if(fmt == 1){
            const float* s = (const float*)src;
            float2 p0 = *(const float2*)(s + cb);
            float2 p1 = *(const float2*)(s + cb + 8);
            w = f2e4m3(p0.x) | (f2e4m3(p0.y)<<8) | (f2e4m3(p1.x)<<16) | (f2e4m3(p1.y)<<24);
        } else if(fmt == 2){
            const __nv_bfloat16* s = (const __nv_bfloat16*)src;
            __nv_bfloat16 h0[2], h1[2];
            *(uint32_t*)h0 = *(const uint32_t*)(s + cb);
            *(uint32_t*)h1 = *(const uint32_t*)(s + cb + 8);
            w = f2e4m3(__bfloat162float(h0[0])) | (f2e4m3(__bfloat162float(h0[1]))<<8)
              | (f2e4m3(__bfloat162float(h1[0]))<<16) | (f2e4m3(__bfloat162float(h1[1]))<<24);
        } else {
            const uint8_t* s = (const uint8_t*)src;
            uint32_t lo = *(const uint16_t*)(s + cb);
            uint32_t hi = *(const uint16_t*)(s + cb + 8);
            w = lo | (hi << 16);
        }
        ((uint32_t*)dst)[widx] = w;
    }
}

// ---- activation fake-quant -> permuted e4m3 bytes + scale ----
__global__ void k_quant_x(const float* __restrict__ x, uint8_t* __restrict__ xq,
                          float* __restrict__ xs){
    int gidx = (int)(((size_t)blockIdx.x*blockDim.x + threadIdx.x) >> 5);
    int lane = threadIdx.x & 31;
    if(gidx >= M_DIM*KB_H) return;
    int row = gidx / KB_H, g = gidx % KB_H;
    float4 v = ((const float4*)(x + (size_t)row*H_DIM + g*128))[lane];
    float am = fmaxf(fmaxf(fabsf(v.x),fabsf(v.y)), fmaxf(fabsf(v.z),fabsf(v.w)));
#pragma unroll
    for(int o = 16; o; o >>= 1) am = fmaxf(am, __shfl_xor_sync(0xffffffffu, am, o));
    float s = fmaxf(__fdiv_rn(am, 448.0f), 1e-12f);
    uint32_t q0 = fq8(v.x,s), q1 = fq8(v.y,s), q2 = fq8(v.z,s), q3 = fq8(v.w,s);
    int ks = lane >> 2, hi2 = (lane >> 1) & 1;
    int p1 = (2*(lane&1))*32 + ks*4 + hi2*2;
    int p2 = p1 + 32;
    uint8_t* base = xq + (size_t)row*H_DIM + g*128;
    *(uint16_t*)(base + p1) = (uint16_t)(q0 | (q1<<8));
    *(uint16_t*)(base + p2) = (uint16_t)(q2 | (q3<<8));
    if(lane == 0) xs[(size_t)row*KB_H + g] = s;
}

// =====================================================================
// GEMM: 128x128 CTA tile, 8 warps (4m x 2n), K-chunk = 128 B,
// 3-stage cp.async pipeline, r-major layout -> LDS.128 fragments.
// Per half-chunk (h): A loaded+cvt ONCE, reused across matrices & nh.
// Scale fold per (h, matrix, nh) — same per-128K fp32 scales.
// =====================================================================
#define SMB 144
#define BUF (128*SMB)   // 18432 bytes per buffer per matrix

__device__ __forceinline__ void fold_q(float part[2][4][4], float acc[2][8][4], int nh,
                                       const float s[2][2]){
#pragma unroll
    for(int mi=0;mi<2;mi++)
#pragma unroll
        for(int ni=0;ni<4;ni++){
            float* a = acc[mi][nh*4+ni];
            a[0] = fmaf(part[mi][ni][0], s[mi][0], a[0]);
            a[1] = fmaf(part[mi][ni][1], s[mi][0], a[1]);
            a[2] = fmaf(part[mi][ni][2], s[mi][1], a[2]);
            a[3] = fmaf(part[mi][ni][3], s[mi][1], a[3]);
        }
}
#define ZERO_PART(p) {_Pragma("unroll") for(int _a=0;_a<2;_a++) _Pragma("unroll") for(int _b=0;_b<4;_b++) _Pragma("unroll") for(int _c=0;_c<4;_c++) (p)[_a][_b][_c]=0.f;}

// load + cvt A fragments for one half-chunk: af[k][mi][4]
__device__ __forceinline__ void load_a(const uint8_t* bA, int wm, int q, int r, int h,
                                       unsigned af[4][2][4]){
#pragma unroll
    for(int mi=0;mi<2;mi++){
        const uint8_t* ap = bA + (wm*32+mi*16+q)*SMB + r*32 + h*16;
        uint4 w0 = *(const uint4*)ap;
        uint4 w1 = *(const uint4*)(ap + 8*SMB);
#pragma unroll
        for(int k=0;k<4;k++){
            unsigned u0 = ((const unsigned*)&w0)[k];
            unsigned u1 = ((const unsigned*)&w1)[k];
            af[k][mi][0] = cvt8((unsigned short)u0);
            af[k][mi][2] = cvt8((unsigned short)(u0>>16));
            af[k][mi][1] = cvt8((unsigned short)u1);
            af[k][mi][3] = cvt8((unsigned short)(u1>>16));
        }
    }
}

// B quarter (4 n-cols of 8) for one half-chunk + MMA into part
__device__ __forceinline__ void mma_quarter(const uint8_t* bBw, int q, int r, int h, int nh,
                                            unsigned af[4][2][4], float part[2][4][4]){
    uint4 B4[4];
#pragma unroll
    for(int ni=0;ni<4;ni++)
        B4[ni] = *(const uint4*)(bBw + ((nh*4+ni)*8+q)*SMB + r*32 + h*16);
#pragma unroll
    for(int k=0;k<4;k++){
#pragma unroll
        for(int ni=0;ni<4;ni++){
            unsigned wb = ((const unsigned*)&B4[ni])[k];
            unsigned b0 = cvt8((unsigned short)wb);
            unsigned b1 = cvt8((unsigned short)(wb>>16));
#pragma unroll
            for(int mi=0;mi<2;mi++)
                mma_f16(part[mi][ni], af[k][mi][0], af[k][mi][1], af[k][mi][2], af[k][mi][3], b0, b1);
        }
    }
}

// ---- fused gate+up GEMM + SwiGLU + hidden quant (permuted fp8 out) ----
__global__ void __launch_bounds__(256, 1)
k_gemm_gu(const uint8_t* __restrict__ Aq, const float* __restrict__ As,
          const uint8_t* __restrict__ Wg, const float* __restrict__ Wsg,
          const uint8_t* __restrict__ Wu, const float* __restrict__ Wsu,
          uint8_t* __restrict__ hq, float* __restrict__ hs){
    extern __shared__ uint8_t sm8[];
    const int K = H_DIM, KS = KB_H, NK = KB_H;
    const int tid = threadIdx.x, wid = tid>>5, lane = tid&31;
    const int q = lane>>2, r = lane&3;
    const int wm = wid&3, wn = wid>>2;
    const int m0 = blockIdx.x<<7, n0 = blockIdx.y<<7;
    const float* wsgr = Wsg + (size_t)blockIdx.y*KS;
    const float* wsur = Wsu + (size_t)blockIdx.y*KS;

    // 3 stages x [A | Bg | Bu]
    float accG[2][8][4], accU[2][8][4];
#pragma unroll
    for(int a=0;a<2;a++)
#pragma unroll
        for(int b=0;b<8;b++)
#pragma unroll
            for(int c=0;c<4;c++){ accG[a][b][c]=0.f; accU[a][b][c]=0.f; }

    auto fill = [&](int kc, int st){
        uint8_t* base0 = sm8 + st*(3*BUF);
#pragma unroll
        for(int j=0;j<12;j++){
            int idx = tid + j*256;
            int mat = idx >> 10, rem = idx & 1023;
            int row = rem >> 3, u = rem & 7;
            const uint8_t* g = (mat==0) ? Aq + (size_t)(m0+row)*K
                             : (mat==1) ? Wg + (size_t)(n0+row)*K
                                        : Wu + (size_t)(n0+row)*K;
            cpasync16(base0 + mat*BUF + row*SMB + u*16, g + kc*128 + u*16);
        }
        asm volatile("cp.async.commit_group;\n");
    };

    fill(0, 0);
    fill(1, 1);
    for(int kc = 0; kc < NK; kc++){
        int st = kc % 3;
        if(kc + 1 < NK) asm volatile("cp.async.wait_group 1;\n");
        else            asm volatile("cp.async.wait_group 0;\n");
        __syncthreads();
        if(kc + 2 < NK) fill(kc+2, (kc+2)%3);

        const uint8_t* bA  = sm8 + st*(3*BUF);
        const uint8_t* bBg = bA + BUF + (wn*64)*SMB;
        const uint8_t* bBu = bA + 2*BUF + (wn*64)*SMB;

        int r0 = m0 + wm*32 + q;
        float a0 = As[(size_t)r0*KS + kc],      a1 = As[(size_t)(r0+8)*KS + kc];
        float a2 = As[(size_t)(r0+16)*KS + kc], a3 = As[(size_t)(r0+24)*KS + kc];
        float swg = wsgr[kc], swu = wsur[kc];
        float sg[2][2] = {{a0*swg, a1*swg},{a2*swg, a3*swg}};
        float su[2][2] = {{a0*swu, a1*swu},{a2*swu, a3*swu}};

#pragma unroll
        for(int h=0; h<2; h++){
            unsigned af[4][2][4];
            load_a(bA, wm, q, r, h, af);
            float part[2][4][4];
#pragma unroll
            for(int nh=0; nh<2; nh++){
                ZERO_PART(part);
                mma_quarter(bBg, q, r, h, nh, af, part);
                fold_q(part, accG, nh, sg);
                ZERO_PART(part);
                mma_quarter(bBu, q, r, h, nh, af, part);
                fold_q(part, accU, nh, su);
            }
        }
        // no trailing sync: next iteration's top sync orders buffer reuse
    }

    // epilogue: h = silu(gate)*up; per-row amax; quantize (permuted) + hs
#pragma unroll
    for(int mi=0;mi<2;mi++)
#pragma unroll
        for(int ni=0;ni<8;ni++)
#pragma unroll
            for(int c=0;c<4;c++){
                float g = accG[mi][ni][c];
                accG[mi][ni][c] = g * sigmoid_precise(g) * accU[mi][ni][c];
            }
    float* red = (float*)sm8;   // stage-0 A region; last chunks used stage (NK-1)%3
#pragma unroll
    for(int mi=0;mi<2;mi++){
        float a0 = 0.f, a1 = 0.f;
#pragma unroll
        for(int ni=0;ni<8;ni++){
            a0 = fmaxf(a0, fmaxf(fabsf(accG[mi][ni][0]), fabsf(accG[mi][ni][1])));
            a1 = fmaxf(a1, fmaxf(fabsf(accG[mi][ni][2]), fabsf(accG[mi][ni][3])));
        }
        a0 = fmaxf(a0, __shfl_xor_sync(0xffffffffu, a0, 1));
        a0 = fmaxf(a0, __shfl_xor_sync(0xffffffffu, a0, 2));
        a1 = fmaxf(a1, __shfl_xor_sync(0xffffffffu, a1, 1));
        a1 = fmaxf(a1, __shfl_xor_sync(0xffffffffu, a1, 2));
        if(r == 0){
            int rl = wm*32 + mi*16 + q;
            red[wn*128 + rl] = a0;
            red[wn*128 + rl + 8] = a1;
        }
    }
    __syncthreads();
    const int gidx = blockIdx.y;
#pragma unroll
    for(int mi=0;mi<2;mi++){
        int rl0 = wm*32 + mi*16 + q;
        float am0 = fmaxf(red[rl0], red[128+rl0]);
        float am1 = fmaxf(red[rl0+8], red[128+rl0+8]);
        float s0 = fmaxf(__fdiv_rn(am0, 448.0f), 1e-12f);
        float s1 = fmaxf(__fdiv_rn(am1, 448.0f), 1e-12f);
        if(wn == 0 && r == 0){
            hs[(size_t)(m0+rl0)*KB_I + gidx] = s0;
            hs[(size_t)(m0+rl0+8)*KB_I + gidx] = s1;
        }
#pragma unroll
        for(int ni=0;ni<8;ni+=2){
            size_t coff = (size_t)n0 + r*32 + (wn*4 + (ni>>1))*4;
            uint32_t w0 = fq8(accG[mi][ni][0],s0)   | (fq8(accG[mi][ni][1],s0)<<8)
                        | (fq8(accG[mi][ni+1][0],s0)<<16) | (fq8(accG[mi][ni+1][1],s0)<<24);
            uint32_t w1 = fq8(accG[mi][ni][2],s1)   | (fq8(accG[mi][ni][3],s1)<<8)
                        | (fq8(accG[mi][ni+1][2],s1)<<16) | (fq8(accG[mi][ni+1][3],s1)<<24);
            *(uint32_t*)(hq + (size_t)(m0+rl0)*I_DIM + coff)   = w0;
            *(uint32_t*)(hq + (size_t)(m0+rl0+8)*I_DIM + coff) = w1;
        }
    }
}

// ---- down GEMM: out = (hq*hs) @ (Wd*Wsd)^T ----
__global__ void __launch_bounds__(256, 1)
k_gemm_dn(const uint8_t* __restrict__ Aq, const float* __restrict__ As,
          const uint8_t* __restrict__ W,  const float* __restrict__ Ws,
          float* __restrict__ out){
    extern __shared__ uint8_t sm8[];
    const int K = I_DIM, KS = KB_I, NK = KB_I, N = H_DIM;
    const int tid = threadIdx.x, wid = tid>>5, lane = tid&31;
    const int q = lane>>2, r = lane&3;
    const int wm = wid&3, wn = wid>>2;
    const int m0 = blockIdx.x<<7, n0 = blockIdx.y<<7;
    const float* wsr = Ws + (size_t)blockIdx.y*KS;

    float acc[2][8][4];
#pragma unroll
    for(int a=0;a<2;a++)
#pragma unroll
        for(int b=0;b<8;b++)
#pragma unroll
            for(int c=0;c<4;c++) acc[a][b][c]=0.f;

    auto fill = [&](int kc, int st){
        uint8_t* base0 = sm8 + st*(2*BUF);
#pragma unroll
        for(int j=0;j<8;j++){
            int idx = tid + j*256;
            int mat = idx >> 10, rem = idx & 1023;
            int row = rem >> 3, u = rem & 7;
            const uint8_t* g = mat ? W + (size_t)(n0+row)*K : Aq + (size_t)(m0+row)*K;
            cpasync16(base0 + mat*BUF + row*SMB + u*16, g + kc*128 + u*16);
        }
        asm volatile("cp.async.commit_group;\n");
    };

    fill(0, 0);
    fill(1, 1);
    for(int kc = 0; kc < NK; kc++){
        int st = kc % 3;
        if(kc + 1 < NK) asm volatile("cp.async.wait_group 1;\n");
        else            asm volatile("cp.async.wait_group 0;\n");
        __syncthreads();
        if(kc + 2 < NK) fill(kc+2, (kc+2)%3);

        const uint8_t* bA = sm8 + st*(2*BUF);
        const uint8_t* bB = bA + BUF + (wn*64)*SMB;

        int r0 = m0 + wm*32 + q;
        float a0 = As[(size_t)r0*KS + kc],      a1 = As[(size_t)(r0+8)*KS + kc];
        float a2 = As[(size_t)(r0+16)*KS + kc], a3 = As[(size_t)(r0+24)*KS + kc];
        float sw = wsr[kc];
        float s[2][2] = {{a0*sw, a1*sw},{a2*sw, a3*sw}};

#pragma unroll
        for(int h=0; h<2; h++){
            unsigned af[4][2][4];
            load_a(bA, wm, q, r, h, af);
            float part[2][4][4];
#pragma unroll
            for(int nh=0; nh<2; nh++){
                ZERO_PART(part);
                mma_quarter(bB, q, r, h, nh, af, part);
                fold_q(part, acc, nh, s);
            }
        }
    }
#pragma unroll
    for(int mi=0;mi<2;mi++){
        int r0 = m0 + wm*32 + mi*16 + q;
#pragma unroll
        for(int ni=0;ni<8;ni++){
            int c = n0 + wn*64 + ni*8 + r*2;
            *(float2*)(out + (size_t)r0*N + c)     = make_float2(acc[mi][ni][0], acc[mi][ni][1]);
            *(float2*)(out + (size_t)(r0+8)*N + c) = make_float2(acc[mi][ni][2], acc[mi][ni][3]);
        }
    }
}

extern "C" void kernel_launch(void* const* d_in, const int* in_sizes, int n_in,
                              void* d_out, int out_size){
    const float* x = (const float*)d_in[0];
    const void*  wg = d_in[1]; const float* wgs = (const float*)d_in[2];
    const void*  wu = d_in[3]; const float* wus = (const float*)d_in[4];
    const void*  wd = d_in[5]; const float* wds = (const float*)d_in[6];
    float* out = (float*)d_out;

    uint8_t *p_wg, *p_wu, *p_wd, *p_xq, *p_hq;
    float *p_xs, *p_hs;
    cudaGetSymbolAddress((void**)&p_wg, g_wg);
    cudaGetSymbolAddress((void**)&p_wu, g_wu);
    cudaGetSymbolAddress((void**)&p_wd, g_wd);
    cudaGetSymbolAddress((void**)&p_xq, g_xq);
    cudaGetSymbolAddress((void**)&p_xs, g_xs);
    cudaGetSymbolAddress((void**)&p_hq, g_hq);
    cudaGetSymbolAddress((void**)&p_hs, g_hs);

    static bool attr_set = false;
    const int smem_gu = 9*BUF;  // 165888 (3 stages x 3 matrices)
    const int smem_dn = 6*BUF;  // 110592 (3 stages x 2 matrices)
    if(!attr_set){
        cudaFuncSetAttribute(k_gemm_gu, cudaFuncAttributeMaxDynamicSharedMemorySize, smem_gu);
        cudaFuncSetAttribute(k_gemm_dn, cudaFuncAttributeMaxDynamicSharedMemorySize, smem_dn);
        attr_set = true;
    }

    k_quant_x<<<(M_DIM*KB_H)/8, 256>>>(x, p_xq, p_xs);
    k_detect<<<1, 256>>>(wg);
    k_convert<<<2048, 256>>>(wg, p_wg, (size_t)I_DIM*H_DIM);
    k_convert<<<2048, 256>>>(wu, p_wu, (size_t)I_DIM*H_DIM);
    k_convert<<<2048, 256>>>(wd, p_wd, (size_t)H_DIM*I_DIM);

    dim3 gGU(M_DIM/128, I_DIM/128);
    k_gemm_gu<<<gGU, 256, smem_gu>>>(p_xq, p_xs, p_wg, wgs, p_wu, wus, p_hq, p_hs);

    dim3 gD(M_DIM/128, H_DIM/128);
    k_gemm_dn<<<gD, 256, smem_dn>>>(p_hq, p_hs, p_wd, wds, out);
}

// round 17
// speedup vs baseline: 1.6494x; 1.6494x over previous
#include <cuda_runtime.h>
#include <cuda_fp16.h>
#include <cuda_bf16.h>
#include <cuda_fp8.h>
#include <cstdint>

#define M_DIM 4096
#define H_DIM 4096
#define I_DIM 14336
#define KB_H (H_DIM/128)
#define KB_I (I_DIM/128)

// ---- static scratch: quantized tensors as r-major-permuted e4m3 bytes ----
// within each 128-byte K-chunk row, col c (ks=c>>4, cc=c&15, r=(cc&7)>>1,
// hi=cc>>3, lo=cc&1) lives at byte  r*32 + ks*4 + hi*2 + lo.
__device__ int g_fmt;
__device__ uint8_t g_wg[(size_t)I_DIM*H_DIM];
__device__ uint8_t g_wu[(size_t)I_DIM*H_DIM];
__device__ uint8_t g_wd[(size_t)H_DIM*I_DIM];
__device__ uint8_t g_xq[(size_t)M_DIM*H_DIM];
__device__ float   g_xs[(size_t)M_DIM*KB_H];
__device__ uint8_t g_hq[(size_t)M_DIM*I_DIM];
__device__ float   g_hs[(size_t)M_DIM*KB_I];

// ---- scalar helpers ----
__device__ __forceinline__ float fp8_to_f32(unsigned char b){
    __half_raw hr = __nv_cvt_fp8_to_halfraw((__nv_fp8_storage_t)b, __NV_E4M3);
    return __half2float(*(__half*)&hr);
}
__device__ __forceinline__ bool fp8_rt(float v){
    if(!isfinite(v) || fabsf(v) > 448.0f) return false;
    __nv_fp8_storage_t b = __nv_cvt_float_to_fp8(v, __NV_SATFINITE, __NV_E4M3);
    return fp8_to_f32((unsigned char)b) == v;
}
__device__ __forceinline__ uint32_t fq8(float v, float s){
    return (uint32_t)(uint8_t)__nv_cvt_float_to_fp8(__fdiv_rn(v, s), __NV_SATFINITE, __NV_E4M3);
}
__device__ __forceinline__ uint32_t f2e4m3(float v){
    return (uint32_t)(uint8_t)__nv_cvt_float_to_fp8(v, __NV_SATFINITE, __NV_E4M3);
}
__device__ __forceinline__ float exp_precise(float x){
    float n = rintf(x * 1.4426950408889634f);
    float r = fmaf(n, -0.693359375f, x);
    r = fmaf(n, 2.12194440e-4f, r);
    float p = 1.9841269841e-4f;
    p = fmaf(p, r, 1.3888888888e-3f);
    p = fmaf(p, r, 8.3333333333e-3f);
    p = fmaf(p, r, 4.1666666667e-2f);
    p = fmaf(p, r, 1.6666666667e-1f);
    p = fmaf(p, r, 0.5f);
    p = fmaf(p, r, 1.0f);
    p = fmaf(p, r, 1.0f);
    return ldexpf(p, (int)n);
}
__device__ __forceinline__ float sigmoid_precise(float x){
    float ax = fminf(fabsf(x), 87.0f);
    float e = exp_precise(-ax);
    float den = 1.0f + e;
    return (x >= 0.0f) ? __fdiv_rn(1.0f, den) : __fdiv_rn(e, den);
}
__device__ __forceinline__ void cpasync16(void* s, const void* g){
    unsigned sa = (unsigned)__cvta_generic_to_shared(s);
    asm volatile("cp.async.cg.shared.global [%0], [%1], 16;\n" :: "r"(sa), "l"(g));
}
__device__ __forceinline__ unsigned cvt8(unsigned short s){
    unsigned r;
    asm("cvt.rn.f16x2.e4m3x2 %0, %1;" : "=r"(r) : "h"(s));
    return r;
}
__device__ __forceinline__ void mma_f16(float* c, unsigned a0, unsigned a1, unsigned a2, unsigned a3,
                                        unsigned b0, unsigned b1){
    asm volatile("mma.sync.aligned.m16n8k16.row.col.f32.f16.f16.f32 "
        "{%0,%1,%2,%3}, {%4,%5,%6,%7}, {%8,%9}, {%0,%1,%2,%3};\n"
        : "+f"(c[0]), "+f"(c[1]), "+f"(c[2]), "+f"(c[3])
        : "r"(a0), "r"(a1), "r"(a2), "r"(a3), "r"(b0), "r"(b1));
}

// ---- format detection ----
__global__ void k_detect(const void* __restrict__ w){
    int tid = threadIdx.x;
    int ok32 = 1, ok16 = 1;
    for(int i = tid; i < 2048; i += blockDim.x){
        ok32 = ok32 && fp8_rt(((const float*)w)[i]);
        ok16 = ok16 && fp8_rt(__bfloat162float(((const __nv_bfloat16*)w)[i]));
    }
    int a32 = __syncthreads_and(ok32);
    int a16 = __syncthreads_and(ok16);
    if(tid == 0) g_fmt = a32 ? 1 : (a16 ? 2 : 0);
}

// ---- weight convert -> r-major permuted e4m3 bytes (exact) ----
__global__ void k_convert(const void* __restrict__ src, uint8_t* __restrict__ dst, size_t n){
    int fmt = g_fmt;
    size_t i = (size_t)blockIdx.x*blockDim.x + threadIdx.x;
    size_t stride = (size_t)gridDim.x*blockDim.x;
    size_t nw = n >> 2;
    for(size_t widx = i; widx < nw; widx += stride){
        size_t chunk = widx >> 5;
        int o = (int)(widx & 31);
        int r = o >> 3, ks = o & 7;
        size_t cb = chunk*128 + (size_t)ks*16 + 2*r;
        uint32_t w;
        if(fmt == 1){
            const float* s = (const float*)src;
            float2 p0 = *(const float2*)(s + cb);
            float2 p1 = *(const float2*)(s + cb + 8);
            w = f2e4m3(p0.x) | (f2e4m3(p0.y)<<8) | (f2e4m3(p1.x)<<16) | (f2e4m3(p1.y)<<24);
        } else if(fmt == 2){
            const __nv_bfloat16* s = (const __nv_bfloat16*)src;
            __nv_bfloat16 h0[2], h1[2];
            *(uint32_t*)h0 = *(const uint32_t*)(s + cb);
            *(uint32_t*)h1 = *(const uint32_t*)(s + cb + 8);
            w = f2e4m3(__bfloat162float(h0[0])) | (f2e4m3(__bfloat162float(h0[1]))<<8)
              | (f2e4m3(__bfloat162float(h1[0]))<<16) | (f2e4m3(__bfloat162float(h1[1]))<<24);
        } else {
            const uint8_t* s = (const uint8_t*)src;
            uint32_t lo = *(const uint16_t*)(s + cb);
            uint32_t hi = *(const uint16_t*)(s + cb + 8);
            w = lo | (hi << 16);
        }
        ((uint32_t*)dst)[widx] = w;
    }
}

// ---- activation fake-quant -> permuted e4m3 bytes + scale ----
__global__ void k_quant_x(const float* __restrict__ x, uint8_t* __restrict__ xq,
                          float* __restrict__ xs){
    int gidx = (int)(((size_t)blockIdx.x*blockDim.x + threadIdx.x) >> 5);
    int lane = threadIdx.x & 31;
    if(gidx >= M_DIM*KB_H) return;
    int row = gidx / KB_H, g = gidx % KB_H;
    float4 v = ((const float4*)(x + (size_t)row*H_DIM + g*128))[lane];
    float am = fmaxf(fmaxf(fabsf(v.x),fabsf(v.y)), fmaxf(fabsf(v.z),fabsf(v.w)));
#pragma unroll
    for(int o = 16; o; o >>= 1) am = fmaxf(am, __shfl_xor_sync(0xffffffffu, am, o));
    float s = fmaxf(__fdiv_rn(am, 448.0f), 1e-12f);
    uint32_t q0 = fq8(v.x,s), q1 = fq8(v.y,s), q2 = fq8(v.z,s), q3 = fq8(v.w,s);
    int ks = lane >> 2, hi2 = (lane >> 1) & 1;
    int p1 = (2*(lane&1))*32 + ks*4 + hi2*2;
    int p2 = p1 + 32;
    uint8_t* base = xq + (size_t)row*H_DIM + g*128;
    *(uint16_t*)(base + p1) = (uint16_t)(q0 | (q1<<8));
    *(uint16_t*)(base + p2) = (uint16_t)(q2 | (q3<<8));
    if(lane == 0) xs[(size_t)row*KB_H + g] = s;
}

// =====================================================================
// GEMM: 128x128 CTA tile, 8 warps (4m x 2n), K-chunk = 128 B,
// 3-stage cp.async pipeline (wait_group 1), r-major layout -> LDS.128
// fragments, cvt in-loop (R14 register budget — NO A hoist).
// =====================================================================
#define SMB 144
#define BUF (128*SMB)   // 18432 bytes per buffer per matrix

// one nh half (B cols [nh*32, nh*32+32)) over a full 128-K chunk
__device__ __forceinline__ void pass2(const uint8_t* bA, const uint8_t* bBw,
                                      int wm, int q, int r, int nh, float part[2][4][4]){
#pragma unroll
    for(int h=0; h<2; h++){
        uint4 A4[2][2];
#pragma unroll
        for(int mi=0;mi<2;mi++){
            const uint8_t* ap = bA + (wm*32+mi*16+q)*SMB + r*32 + h*16;
            A4[mi][0] = *(const uint4*)ap;
            A4[mi][1] = *(const uint4*)(ap + 8*SMB);
        }
        uint4 B4[4];
#pragma unroll
        for(int ni=0;ni<4;ni++)
            B4[ni] = *(const uint4*)(bBw + ((nh*4+ni)*8+q)*SMB + r*32 + h*16);
#pragma unroll
        for(int k=0;k<4;k++){
            unsigned af[2][4];
#pragma unroll
            for(int mi=0;mi<2;mi++){
                unsigned w0 = ((const unsigned*)&A4[mi][0])[k];
                unsigned w1 = ((const unsigned*)&A4[mi][1])[k];
                af[mi][0] = cvt8((unsigned short)w0);
                af[mi][2] = cvt8((unsigned short)(w0>>16));
                af[mi][1] = cvt8((unsigned short)w1);
                af[mi][3] = cvt8((unsigned short)(w1>>16));
            }
#pragma unroll
            for(int ni=0;ni<4;ni++){
                unsigned wb = ((const unsigned*)&B4[ni])[k];
                unsigned b0 = cvt8((unsigned short)wb);
                unsigned b1 = cvt8((unsigned short)(wb>>16));
#pragma unroll
                for(int mi=0;mi<2;mi++)
                    mma_f16(part[mi][ni], af[mi][0], af[mi][1], af[mi][2], af[mi][3], b0, b1);
            }
        }
    }
}

__device__ __forceinline__ void fold_q(float part[2][4][4], float acc[2][8][4], int nh,
                                       const float s[2][2]){
#pragma unroll
    for(int mi=0;mi<2;mi++)
#pragma unroll
        for(int ni=0;ni<4;ni++){
            float* a = acc[mi][nh*4+ni];
            a[0] = fmaf(part[mi][ni][0], s[mi][0], a[0]);
            a[1] = fmaf(part[mi][ni][1], s[mi][0], a[1]);
            a[2] = fmaf(part[mi][ni][2], s[mi][1], a[2]);
            a[3] = fmaf(part[mi][ni][3], s[mi][1], a[3]);
        }
}
#define ZERO_PART(p) {_Pragma("unroll") for(int _a=0;_a<2;_a++) _Pragma("unroll") for(int _b=0;_b<4;_b++) _Pragma("unroll") for(int _c=0;_c<4;_c++) (p)[_a][_b][_c]=0.f;}

// ---- fused gate+up GEMM + SwiGLU + hidden quant (permuted fp8 out) ----
__global__ void __launch_bounds__(256, 1)
k_gemm_gu(const uint8_t* __restrict__ Aq, const float* __restrict__ As,
          const uint8_t* __restrict__ Wg, const float* __restrict__ Wsg,
          const uint8_t* __restrict__ Wu, const float* __restrict__ Wsu,
          uint8_t* __restrict__ hq, float* __restrict__ hs){
    extern __shared__ uint8_t sm8[];
    const int K = H_DIM, KS = KB_H, NK = KB_H;
    const int tid = threadIdx.x, wid = tid>>5, lane = tid&31;
    const int q = lane>>2, r = lane&3;
    const int wm = wid&3, wn = wid>>2;
    const int m0 = blockIdx.x<<7, n0 = blockIdx.y<<7;
    const float* wsgr = Wsg + (size_t)blockIdx.y*KS;
    const float* wsur = Wsu + (size_t)blockIdx.y*KS;

    float accG[2][8][4], accU[2][8][4];
#pragma unroll
    for(int a=0;a<2;a++)
#pragma unroll
        for(int b=0;b<8;b++)
#pragma unroll
            for(int c=0;c<4;c++){ accG[a][b][c]=0.f; accU[a][b][c]=0.f; }

    // stage st holds [A | Bg | Bu] at sm8 + st*3*BUF
    auto fill = [&](int kc, int st){
        uint8_t* base0 = sm8 + st*(3*BUF);
#pragma unroll
        for(int j=0;j<12;j++){
            int idx = tid + j*256;
            int mat = idx >> 10, rem = idx & 1023;
            int row = rem >> 3, u = rem & 7;
            const uint8_t* g = (mat==0) ? Aq + (size_t)(m0+row)*K
                             : (mat==1) ? Wg + (size_t)(n0+row)*K
                                        : Wu + (size_t)(n0+row)*K;
            cpasync16(base0 + mat*BUF + row*SMB + u*16, g + kc*128 + u*16);
        }
        asm volatile("cp.async.commit_group;\n");
    };

    fill(0, 0);
    fill(1, 1);
    for(int kc = 0; kc < NK; kc++){
        int st = kc % 3;
        if(kc + 1 < NK) asm volatile("cp.async.wait_group 1;\n");
        else            asm volatile("cp.async.wait_group 0;\n");
        __syncthreads();
        if(kc + 2 < NK) fill(kc+2, (kc+2)%3);

        const uint8_t* bA  = sm8 + st*(3*BUF);
        const uint8_t* bBg = bA + BUF + (wn*64)*SMB;
        const uint8_t* bBu = bA + 2*BUF + (wn*64)*SMB;

        int r0 = m0 + wm*32 + q;
        float a0 = As[(size_t)r0*KS + kc],      a1 = As[(size_t)(r0+8)*KS + kc];
        float a2 = As[(size_t)(r0+16)*KS + kc], a3 = As[(size_t)(r0+24)*KS + kc];
        float swg = wsgr[kc], swu = wsur[kc];
        float sg[2][2] = {{a0*swg, a1*swg},{a2*swg, a3*swg}};
        float su[2][2] = {{a0*swu, a1*swu},{a2*swu, a3*swu}};

        float part[2][4][4];
#pragma unroll
        for(int nh=0; nh<2; nh++){
            ZERO_PART(part);
            pass2(bA, bBg, wm, q, r, nh, part);
            fold_q(part, accG, nh, sg);
            ZERO_PART(part);
            pass2(bA, bBu, wm, q, r, nh, part);
            fold_q(part, accU, nh, su);
        }
        // no trailing sync: next iteration's top sync orders buffer reuse
    }

    // epilogue: h = silu(gate)*up; per-row amax; quantize (permuted) + hs
#pragma unroll
    for(int mi=0;mi<2;mi++)
#pragma unroll
        for(int ni=0;ni<8;ni++)
#pragma unroll
            for(int c=0;c<4;c++){
                float g = accG[mi][ni][c];
                accG[mi][ni][c] = g * sigmoid_precise(g) * accU[mi][ni][c];
            }
    float* red = (float*)sm8;
#pragma unroll
    for(int mi=0;mi<2;mi++){
        float a0 = 0.f, a1 = 0.f;
#pragma unroll
        for(int ni=0;ni<8;ni++){
            a0 = fmaxf(a0, fmaxf(fabsf(accG[mi][ni][0]), fabsf(accG[mi][ni][1])));
            a1 = fmaxf(a1, fmaxf(fabsf(accG[mi][ni][2]), fabsf(accG[mi][ni][3])));
        }
        a0 = fmaxf(a0, __shfl_xor_sync(0xffffffffu, a0, 1));
        a0 = fmaxf(a0, __shfl_xor_sync(0xffffffffu, a0, 2));
        a1 = fmaxf(a1, __shfl_xor_sync(0xffffffffu, a1, 1));
        a1 = fmaxf(a1, __shfl_xor_sync(0xffffffffu, a1, 2));
        if(r == 0){
            int rl = wm*32 + mi*16 + q;
            red[wn*128 + rl] = a0;
            red[wn*128 + rl + 8] = a1;
        }
    }
    __syncthreads();
    const int gidx = blockIdx.y;
#pragma unroll
    for(int mi=0;mi<2;mi++){
        int rl0 = wm*32 + mi*16 + q;
        float am0 = fmaxf(red[rl0], red[128+rl0]);
        float am1 = fmaxf(red[rl0+8], red[128+rl0+8]);
        float s0 = fmaxf(__fdiv_rn(am0, 448.0f), 1e-12f);
        float s1 = fmaxf(__fdiv_rn(am1, 448.0f), 1e-12f);
        if(wn == 0 && r == 0){
            hs[(size_t)(m0+rl0)*KB_I + gidx] = s0;
            hs[(size_t)(m0+rl0+8)*KB_I + gidx] = s1;
        }
#pragma unroll
        for(int ni=0;ni<8;ni+=2){
            size_t coff = (size_t)n0 + r*32 + (wn*4 + (ni>>1))*4;
            uint32_t w0 = fq8(accG[mi][ni][0],s0)   | (fq8(accG[mi][ni][1],s0)<<8)
                        | (fq8(accG[mi][ni+1][0],s0)<<16) | (fq8(accG[mi][ni+1][1],s0)<<24);
            uint32_t w1 = fq8(accG[mi][ni][2],s1)   | (fq8(accG[mi][ni][3],s1)<<8)
                        | (fq8(accG[mi][ni+1][2],s1)<<16) | (fq8(accG[mi][ni+1][3],s1)<<24);
            *(uint32_t*)(hq + (size_t)(m0+rl0)*I_DIM + coff)   = w0;
            *(uint32_t*)(hq + (size_t)(m0+rl0+8)*I_DIM + coff) = w1;
        }
    }
}

// ---- down GEMM: out = (hq*hs) @ (Wd*Wsd)^T ----
__global__ void __launch_bounds__(256, 1)
k_gemm_dn(const uint8_t* __restrict__ Aq, const float* __restrict__ As,
          const uint8_t* __restrict__ W,  const float* __restrict__ Ws,
          float* __restrict__ out){
    extern __shared__ uint8_t sm8[];
    const int K = I_DIM, KS = KB_I, NK = KB_I, N = H_DIM;
    const int tid = threadIdx.x, wid = tid>>5, lane = tid&31;
    const int q = lane>>2, r = lane&3;
    const int wm = wid&3, wn = wid>>2;
    const int m0 = blockIdx.x<<7, n0 = blockIdx.y<<7;
    const float* wsr = Ws + (size_t)blockIdx.y*KS;

    float acc[2][8][4];
#pragma unroll
    for(int a=0;a<2;a++)
#pragma unroll
        for(int b=0;b<8;b++)
#pragma unroll
            for(int c=0;c<4;c++) acc[a][b][c]=0.f;

    auto fill = [&](int kc, int st){
        uint8_t* base0 = sm8 + st*(2*BUF);
#pragma unroll
        for(int j=0;j<8;j++){
            int idx = tid + j*256;
            int mat = idx >> 10, rem = idx & 1023;
            int row = rem >> 3, u = rem & 7;
            const uint8_t* g = mat ? W + (size_t)(n0+row)*K : Aq + (size_t)(m0+row)*K;
            cpasync16(base0 + mat*BUF + row*SMB + u*16, g + kc*128 + u*16);
        }
        asm volatile("cp.async.commit_group;\n");
    };

    fill(0, 0);
    fill(1, 1);
    for(int kc = 0; kc < NK; kc++){
        int st = kc % 3;
        if(kc + 1 < NK) asm volatile("cp.async.wait_group 1;\n");
        else            asm volatile("cp.async.wait_group 0;\n");
        __syncthreads();
        if(kc + 2 < NK) fill(kc+2, (kc+2)%3);

        const uint8_t* bA = sm8 + st*(2*BUF);
        const uint8_t* bB = bA + BUF + (wn*64)*SMB;

        int r0 = m0 + wm*32 + q;
        float a0 = As[(size_t)r0*KS + kc],      a1 = As[(size_t)(r0+8)*KS + kc];
        float a2 = As[(size_t)(r0+16)*KS + kc], a3 = As[(size_t)(r0+24)*KS + kc];
        float sw = wsr[kc];
        float s[2][2] = {{a0*sw, a1*sw},{a2*sw, a3*sw}};

        float part[2][4][4];
#pragma unroll
        for(int nh=0; nh<2; nh++){
            ZERO_PART(part);
            pass2(bA, bB, wm, q, r, nh, part);
            fold_q(part, acc, nh, s);
        }
    }
#pragma unroll
    for(int mi=0;mi<2;mi++){
        int r0 = m0 + wm*32 + mi*16 + q;
#pragma unroll
        for(int ni=0;ni<8;ni++){
            int c = n0 + wn*64 + ni*8 + r*2;
            *(float2*)(out + (size_t)r0*N + c)     = make_float2(acc[mi][ni][0], acc[mi][ni][1]);
            *(float2*)(out + (size_t)(r0+8)*N + c) = make_float2(acc[mi][ni][2], acc[mi][ni][3]);
        }
    }
}

extern "C" void kernel_launch(void* const* d_in, const int* in_sizes, int n_in,
                              void* d_out, int out_size){
    const float* x = (const float*)d_in[0];
    const void*  wg = d_in[1]; const float* wgs = (const float*)d_in[2];
    const void*  wu = d_in[3]; const float* wus = (const float*)d_in[4];
    const void*  wd = d_in[5]; const float* wds = (const float*)d_in[6];
    float* out = (float*)d_out;

    uint8_t *p_wg, *p_wu, *p_wd, *p_xq, *p_hq;
    float *p_xs, *p_hs;
    cudaGetSymbolAddress((void**)&p_wg, g_wg);
    cudaGetSymbolAddress((void**)&p_wu, g_wu);
    cudaGetSymbolAddress((void**)&p_wd, g_wd);
    cudaGetSymbolAddress((void**)&p_xq, g_xq);
    cudaGetSymbolAddress((void**)&p_xs, g_xs);
    cudaGetSymbolAddress((void**)&p_hq, g_hq);
    cudaGetSymbolAddress((void**)&p_hs, g_hs);

    static bool attr_set = false;
    const int smem_gu = 9*BUF;  // 165888 (3 stages x 3 matrices)
    const int smem_dn = 6*BUF;  // 110592 (3 stages x 2 matrices)
    if(!attr_set){
        cudaFuncSetAttribute(k_gemm_gu, cudaFuncAttributeMaxDynamicSharedMemorySize, smem_gu);
        cudaFuncSetAttribute(k_gemm_dn, cudaFuncAttributeMaxDynamicSharedMemorySize, smem_dn);
        attr_set = true;
    }

    k_quant_x<<<(M_DIM*KB_H)/8, 256>>>(x, p_xq, p_xs);
    k_detect<<<1, 256>>>(wg);
    k_convert<<<2048, 256>>>(wg, p_wg, (size_t)I_DIM*H_DIM);
    k_convert<<<2048, 256>>>(wu, p_wu, (size_t)I_DIM*H_DIM);
    k_convert<<<2048, 256>>>(wd, p_wd, (size_t)H_DIM*I_DIM);

    dim3 gGU(M_DIM/128, I_DIM/128);
    k_gemm_gu<<<gGU, 256, smem_gu>>>(p_xq, p_xs, p_wg, wgs, p_wu, wus, p_hq, p_hs);

    dim3 gD(M_DIM/128, H_DIM/128);
    k_gemm_dn<<<gD, 256, smem_dn>>>(p_hq, p_hs, p_wd, wds, out);
}